// round 13
// baseline (speedup 1.0000x reference)
#include <cuda_runtime.h>
#include <cuda_bf16.h>
#include <math.h>

// ---------------------------------------------------------------------------
// MoE router (TOP_K=2, N_EXP=8).
// Output (float32): [0..8) used_capacity | [8..8+R) cb_weight | [8+R..8+2R) sec_mask
//   where R = N*8*C.
//
// Kernel 1 (persistent, 148 CTAs x 1024, one per SM):
//   CTA 1..147: warps 0..27  = zero-fill (grid-stride interleaved STG.128)
//                              -- 28 fill warps/SM: R12 showed 18 warps/SM
//                                 only reaches 4.5 TB/s; ~27 should give ~6.
//               warps 28..31 = router (7 tokens/warp; named barrier 1)
//   CTA 0     : spin-join router -> full-CTA ordered rank scan -> used_capacity.
// Kernel 2 (wide grid): scatter the 2N nonzeros (kernel boundary = fill sync).
// g_done_router: release-fence + atomicAdd; single waiter subtracts target
// after observing it => graph replays start from zero.
// ---------------------------------------------------------------------------

#define N_EXP 8
#define MAXN 65536
#define GRID 148
#define BLOCK 1024
#define FW_PER_CTA 28                                  // fill warps / worker CTA
#define RW_PER_CTA 4                                   // router warps / worker CTA
#define R_TARGET ((GRID - 1) * RW_PER_CTA)             // 588
#define F_THREADS ((long long)(GRID - 1) * FW_PER_CTA * 32)  // 131712

__device__ int          g_eidx[2 * MAXN];
__device__ float        g_pval[2 * MAXN];
__device__ int          g_rank[2 * MAXN];
__device__ unsigned int g_done_router;   // zero-init; self-resetting

__global__ void __launch_bounds__(BLOCK, 1) fused_kernel(
    const float* __restrict__ x, const float* __restrict__ w_g,
    float* __restrict__ out, int N, int C, long long out_elems)
{
    __shared__ float4 ws[N_EXP * 256];          // 32KB w_g (D=1024)
    __shared__ int warpcnt[N_EXP][32];
    __shared__ int basesh[N_EXP][32];
    __shared__ int running[N_EXP];

    const int tid  = threadIdx.x;
    const int warp = tid >> 5;
    const int lane = tid & 31;
    const int b    = blockIdx.x;

    const long long fillF4 = (out_elems - 8) >> 2;       // float4 count
    float4* const   fill4  = reinterpret_cast<float4*>(out + 8);

    if (b != 0) {
        if (warp < FW_PER_CTA) {
            // ========== FILL WARPS: grid-stride interleaved zeroing ==========
            const long long ftid =
                (long long)(b - 1) * FW_PER_CTA * 32 +
                (long long)warp * 32 + lane;
            const float4 z = make_float4(0.f, 0.f, 0.f, 0.f);

            long long i = ftid;
            const long long step4 = 4 * F_THREADS;
            for (; i + 3 * F_THREADS < fillF4; i += step4) {
                fill4[i]                 = z;
                fill4[i + F_THREADS]     = z;
                fill4[i + 2 * F_THREADS] = z;
                fill4[i + 3 * F_THREADS] = z;
            }
            for (; i < fillF4; i += F_THREADS)
                fill4[i] = z;
            return;
        }

        // ============== ROUTER WARPS (28..31): 7-ish tokens/warp ============
        const float4* wg4 = reinterpret_cast<const float4*>(w_g);
        const int rt = (warp - FW_PER_CTA) * 32 + lane;  // 0..127
        for (int idx = rt; idx < N_EXP * 256; idx += RW_PER_CTA * 32)
            ws[idx] = wg4[idx];
        asm volatile("bar.sync 1, %0;" :: "r"(RW_PER_CTA * 32) : "memory");

        const int rw = (b - 1) * RW_PER_CTA + (warp - FW_PER_CTA);

        for (int token = rw; token < N; token += R_TARGET) {
            const float4* x4 =
                reinterpret_cast<const float4*>(x) + (size_t)token * 256;

            float acc[N_EXP];
#pragma unroll
            for (int e = 0; e < N_EXP; e++) acc[e] = 0.0f;

#pragma unroll
            for (int j = 0; j < 8; j++) {
                float4 xv = x4[j * 32 + lane];
#pragma unroll
                for (int e = 0; e < N_EXP; e++) {
                    float4 wv = ws[e * 256 + j * 32 + lane];
                    acc[e] += xv.x * wv.x + xv.y * wv.y +
                              xv.z * wv.z + xv.w * wv.w;
                }
            }

#pragma unroll
            for (int off = 16; off > 0; off >>= 1)
#pragma unroll
                for (int e = 0; e < N_EXP; e++)
                    acc[e] += __shfl_down_sync(0xFFFFFFFFu, acc[e], off);

            if (lane == 0) {
                int e0 = 0; float b0 = acc[0];
#pragma unroll
                for (int e = 1; e < N_EXP; e++)
                    if (acc[e] > b0) { b0 = acc[e]; e0 = e; }
                int e1 = (e0 == 0) ? 1 : 0; float b1 = acc[e1];
#pragma unroll
                for (int e = 0; e < N_EXP; e++)
                    if (e != e0 && acc[e] > b1) { b1 = acc[e]; e1 = e; }

                float sum = 0.0f;
#pragma unroll
                for (int e = 0; e < N_EXP; e++) sum += expf(acc[e] - b0);
                float inv = 1.0f / sum;

                g_eidx[token]     = e0;
                g_eidx[N + token] = e1;
                g_pval[token]     = inv;
                g_pval[N + token] = expf(b1 - b0) * inv;
            }
        }
        __syncwarp();
        if (lane == 0) {
            __threadfence();
            atomicAdd(&g_done_router, 1u);
        }
        return;
    }

    // =================== CTA 0: rank scan + used_capacity ===================
    if (tid < N_EXP) running[tid] = 0;

    if (tid == 0) {
        while (atomicAdd(&g_done_router, 0u) < (unsigned)R_TARGET) { }
        atomicSub(&g_done_router, (unsigned)R_TARGET);   // reset for replay
        __threadfence();
    }
    __syncthreads();

    const int total = 2 * N;
    const int rounds = (total + BLOCK - 1) / BLOCK;
    for (int rd = 0; rd < rounds; rd++) {
        const int i = rd * BLOCK + tid;
        const int e = (i < total) ? g_eidx[i] : -1;

        if (tid < N_EXP * 32) ((int*)warpcnt)[tid] = 0;
        __syncthreads();

        unsigned m = __match_any_sync(0xFFFFFFFFu, e);
        int lrank  = __popc(m & ((1u << lane) - 1u));
        int leader = __ffs(m) - 1;
        if (e >= 0 && lane == leader)
            warpcnt[e][warp] = __popc(m);
        __syncthreads();

        if (warp < N_EXP) {
            int runv = running[warp];
            int v = warpcnt[warp][lane];
            int s = v;
#pragma unroll
            for (int off = 1; off < 32; off <<= 1) {
                int u = __shfl_up_sync(0xFFFFFFFFu, s, off);
                if (lane >= off) s += u;
            }
            basesh[warp][lane] = runv + s - v;
            if (lane == 31) running[warp] = runv + s;
        }
        __syncthreads();

        if (e >= 0)
            g_rank[i] = basesh[e][warp] + lrank;
        __syncthreads();
    }

    // used_capacity (out[0..8) is outside the fill region)
    if (tid < N_EXP) {
        int uc = running[tid];
        if (uc > C) uc = C;
        out[tid] = (float)uc;
    }

    // tail floats not covered by float4 fill (none when C even, but safe)
    {
        long long done = 8 + (((out_elems - 8) >> 2) << 2);
        for (long long i = done + tid; i < out_elems; i += BLOCK)
            out[i] = 0.0f;
    }
}

// ---------------------------------------------------------------------------
// Kernel 2: wide-grid scatter. One thread per routed entry: at most 2 stores
// into the (already-zeroed) output.
// ---------------------------------------------------------------------------
__global__ void __launch_bounds__(256) scatter_kernel(
    float* __restrict__ out, int N, int C)
{
    const int i = blockIdx.x * blockDim.x + threadIdx.x;
    const int total = 2 * N;
    const long long rowsC = (long long)N * N_EXP * (long long)C;

    if (i < total) {
        int r = g_rank[i];
        if (r < C) {
            int e = g_eidx[i];
            int k = (i >= N) ? 1 : 0;
            int n = i - k * N;
            long long pos = ((long long)n * N_EXP + e) * (long long)C + r;
            out[8 + pos]         = g_pval[i];
            out[8 + rowsC + pos] = 1.0f;
        }
    }
}

// ---------------------------------------------------------------------------
extern "C" void kernel_launch(void* const* d_in, const int* in_sizes, int n_in,
                              void* d_out, int out_size)
{
    const float* x   = (const float*)d_in[0];
    const float* w_g = (const float*)d_in[1];
    float* out = (float*)d_out;

    const int D = in_sizes[1] / N_EXP;   // 1024
    const int N = in_sizes[0] / D;       // 4096 tokens

    int C = (int)floorf(2.0f * 1.25f * (float)N / (float)N_EXP);
    C += (C & 1);
    if (C < 4) C = 4;

    // 1) fused: fill (336MB, 28 warps/SM) overlapped with router + rank scan
    fused_kernel<<<GRID, BLOCK>>>(x, w_g, out, N, C, (long long)out_size);

    // 2) wide-grid scatter of the 2N nonzeros
    int sblocks = (2 * N + 255) / 256;
    scatter_kernel<<<sblocks, 256>>>(out, N, C);
}